// round 11
// baseline (speedup 1.0000x reference)
#include <cuda_runtime.h>
#include <cuda_fp16.h>
#include <math.h>
#include <stdint.h>

// Problem constants: B=4, S=2048, D=1024, E=8, K=2, H=2048
#define T_TOK 8192
#define D_DIM 1024
#define H_DIM 2048
#define E_NUM 8
#define A_TOT (2 * T_TOK)             // 16384 assignments
#define A_PAD (A_TOT + E_NUM * 128)   // 17408 padded rows
#define MT_TILES (A_PAD / 128)        // 136 m-tiles

// ---------------- scratch (device globals; no allocations) ------------------
__device__ int   g_topi[A_TOT];
__device__ float g_topw[A_TOT];
__device__ int   g_cnt[E_NUM];
__device__ int   g_poff[E_NUM + 1];
__device__ int   g_cursor[E_NUM];
__device__ int   g_perm[A_PAD];
__device__ float g_pw[A_PAD];
__device__ int   g_slot[A_TOT];
__device__ __half g_xh [(size_t)T_TOK * D_DIM];            // x fp16, 17 MB
__device__ __half g_w1h[(size_t)E_NUM * D_DIM * H_DIM];    // w1 fp16, 34 MB
__device__ __half g_w2h[(size_t)E_NUM * D_DIM * H_DIM];    // w2 fp16, 34 MB
__device__ __half g_h  [(size_t)A_PAD * H_DIM];            // hidden fp16, 71 MB
__device__ float  g_y  [(size_t)A_PAD * D_DIM];            // per-slot out, 71 MB

// ---------------- PTX helpers (generic sm_80+ only) -------------------------
__device__ __forceinline__ uint32_t smem_u32(const void* p) {
    uint32_t a;
    asm("{ .reg .u64 t; cvta.to.shared.u64 t, %1; cvt.u32.u64 %0, t; }" : "=r"(a) : "l"(p));
    return a;
}
__device__ __forceinline__ void cp_async16(uint32_t dst, const void* src) {
    asm volatile("cp.async.cg.shared.global [%0], [%1], 16;" :: "r"(dst), "l"(src) : "memory");
}
__device__ __forceinline__ void cp_commit() {
    asm volatile("cp.async.commit_group;" ::: "memory");
}
__device__ __forceinline__ void ldsm4(uint32_t* r, uint32_t a) {
    asm volatile("ldmatrix.sync.aligned.m8n8.x4.shared.b16 {%0,%1,%2,%3}, [%4];"
                 : "=r"(r[0]), "=r"(r[1]), "=r"(r[2]), "=r"(r[3]) : "r"(a));
}
__device__ __forceinline__ void ldsm4t(uint32_t* r, uint32_t a) {
    asm volatile("ldmatrix.sync.aligned.m8n8.x4.trans.shared.b16 {%0,%1,%2,%3}, [%4];"
                 : "=r"(r[0]), "=r"(r[1]), "=r"(r[2]), "=r"(r[3]) : "r"(a));
}
__device__ __forceinline__ void mma_f16(float* c, const uint32_t* a, const uint32_t* b) {
    asm volatile(
        "mma.sync.aligned.m16n8k16.row.col.f32.f16.f16.f32 "
        "{%0,%1,%2,%3}, {%4,%5,%6,%7}, {%8,%9}, {%0,%1,%2,%3};"
        : "+f"(c[0]), "+f"(c[1]), "+f"(c[2]), "+f"(c[3])
        : "r"(a[0]), "r"(a[1]), "r"(a[2]), "r"(a[3]), "r"(b[0]), "r"(b[1]));
}

// ---------------- kernel: init (counters + padded perm/pw) ------------------
__global__ __launch_bounds__(256) void init_kernel() {
    int i = blockIdx.x * 256 + threadIdx.x;
    if (i < A_PAD) { g_perm[i] = 0; g_pw[i] = 0.f; }
    if (i < E_NUM) g_cnt[i] = 0;
}

// ---------------- kernel: fp32 -> fp16 convert ------------------------------
__global__ __launch_bounds__(256) void cvt_kernel(const float* __restrict__ src,
                                                  __half2* __restrict__ dst) {
    int i = blockIdx.x * 256 + threadIdx.x;      // one float4 per thread
    float4 v = ((const float4*)src)[i];
    dst[2 * i]     = __floats2half2_rn(v.x, v.y);
    dst[2 * i + 1] = __floats2half2_rn(v.z, v.w);
}

// ---------------- kernel: gating (softmax + top-2 + counts) -----------------
__global__ __launch_bounds__(256) void gating_kernel(
    const float* __restrict__ x, const float* __restrict__ gw, const float* __restrict__ gb)
{
    __shared__ float s_gw[D_DIM * E_NUM];
    int tid = threadIdx.x;
    for (int i = tid; i < D_DIM * E_NUM; i += blockDim.x) s_gw[i] = gw[i];
    __syncthreads();

    int warp = tid >> 5, lane = tid & 31;
    int t = blockIdx.x * 8 + warp;
    if (t >= T_TOK) return;

    float acc[E_NUM];
#pragma unroll
    for (int e = 0; e < E_NUM; e++) acc[e] = 0.f;
    const float* xr = x + (size_t)t * D_DIM;
    for (int d = lane; d < D_DIM; d += 32) {
        float xv = xr[d];
        const float* g = s_gw + d * E_NUM;
#pragma unroll
        for (int e = 0; e < E_NUM; e++) acc[e] += xv * g[e];
    }
#pragma unroll
    for (int e = 0; e < E_NUM; e++)
#pragma unroll
        for (int o = 16; o > 0; o >>= 1)
            acc[e] += __shfl_xor_sync(0xffffffffu, acc[e], o);

    if (lane == 0) {
        float logits[E_NUM];
#pragma unroll
        for (int e = 0; e < E_NUM; e++) logits[e] = acc[e] + gb[e];
        float mx = logits[0];
#pragma unroll
        for (int e = 1; e < E_NUM; e++) mx = fmaxf(mx, logits[e]);
        float p[E_NUM], s = 0.f;
#pragma unroll
        for (int e = 0; e < E_NUM; e++) { p[e] = expf(logits[e] - mx); s += p[e]; }
        float inv_s = 1.f / s;
#pragma unroll
        for (int e = 0; e < E_NUM; e++) p[e] *= inv_s;

        int i0 = 0;
#pragma unroll
        for (int e = 1; e < E_NUM; e++) if (p[e] > p[i0]) i0 = e;
        int i1 = (i0 == 0) ? 1 : 0;
#pragma unroll
        for (int e = 0; e < E_NUM; e++)
            if (e != i0 && p[e] > p[i1]) i1 = e;

        float w0 = p[i0], w1 = p[i1];
        float inv = 1.f / (w0 + w1 + 1e-9f);
        g_topi[2 * t] = i0;     g_topw[2 * t] = w0 * inv;
        g_topi[2 * t + 1] = i1; g_topw[2 * t + 1] = w1 * inv;
        atomicAdd(&g_cnt[i0], 1);
        atomicAdd(&g_cnt[i1], 1);
    }
}

// ---------------- kernel: padded offsets -------------------------------------
__global__ void offsets_kernel() {
    if (threadIdx.x == 0) {
        int o = 0;
        for (int e = 0; e < E_NUM; e++) {
            g_poff[e] = o;
            g_cursor[e] = o;
            o += ((g_cnt[e] + 127) & ~127);
        }
        g_poff[E_NUM] = o;
    }
}

// ---------------- kernel: scatter --------------------------------------------
__global__ void scatter_kernel() {
    int a = blockIdx.x * blockDim.x + threadIdx.x;
    if (a >= A_TOT) return;
    int e = g_topi[a];
    int pos = atomicAdd(&g_cursor[e], 1);
    g_perm[pos] = a >> 1;
    g_pw[pos] = g_topw[a];
    g_slot[a] = pos;
}

// ---------------- fp16 mma grouped GEMM --------------------------------------
// Tile 128(M) x 256(N) x 32(Kstage). 256 threads = 8 warps (4m x 2n),
// warp tile 32x128, mma m16n8k16 fp16->fp32 (2 m-frag x 16 n-frag, acc=128 regs).
// A smem [128 m][32 k] half, row stride 80 B (bank-complete r*5 mod 8).
// B smem [32 k][256 n] half, 512 B rows, 16B-chunk XOR swizzle c^(k&7)
//   (row stride 512 B == 0 mod 32 banks, so the XOR alone spans all banks).
// MODE 0: h = relu(xh[perm] @ w1h + b1)  (A gathered via g_perm)
// MODE 1: y = pw * (h @ w2h + b2)
#define A_STAGE_B (128 * 80)                  // 10240
#define B_STAGE_B (32 * 512)                  // 16384
#define STAGE_B (A_STAGE_B + B_STAGE_B)       // 26624
#define GEMM_SMEM (4 * STAGE_B)               // 106496

template<int KDIM, int NTOT, int MODE>
__global__ __launch_bounds__(256, 1) void moe_gemm_kernel(
    const __half* __restrict__ W, const float* __restrict__ bias)
{
    constexpr int NK = KDIM / 32;
    extern __shared__ char smraw[];
    __shared__ int s_perm[128];
    uint32_t smem_base = smem_u32(smraw);

    int tid = threadIdx.x, wid = tid >> 5, lane = tid & 31;
    int m0 = blockIdx.x * 128;

    int e = -1;
#pragma unroll
    for (int i = 0; i < E_NUM; i++)
        if (m0 >= g_poff[i] && m0 < g_poff[i + 1]) e = i;
    if (e < 0) return;
    int n0 = blockIdx.y * 256;

    if (MODE == 0) {
        if (tid < 128) s_perm[tid] = g_perm[m0 + tid];
        __syncthreads();
    }

    const __half* Ag = g_h + (size_t)m0 * KDIM;            // MODE 1 A base
    const __half* Bw = W + (size_t)e * KDIM * NTOT + n0;   // [k][n] row-major

    auto issue_stage = [&](int kt) {
        uint32_t sb = smem_base + (kt & 3) * STAGE_B;
        int k0 = kt * 32;
#pragma unroll
        for (int ii = 0; ii < 2; ii++) {                   // A: 512 chunks
            int i = tid + ii * 256;
            int m = i >> 2, c = i & 3;
            const __half* src = (MODE == 0)
                ? g_xh + (size_t)s_perm[m] * KDIM + k0 + c * 8
                : Ag + (size_t)m * KDIM + k0 + c * 8;
            cp_async16(sb + m * 80 + c * 16, src);
        }
        uint32_t sbB = sb + A_STAGE_B;
#pragma unroll
        for (int ii = 0; ii < 4; ii++) {                   // B: 1024 chunks
            int i = tid + ii * 256;
            int k = i >> 5, c = i & 31;
            cp_async16(sbB + k * 512 + (((c & 7) ^ (k & 7)) << 4) + ((c >> 3) << 7),
                       Bw + (size_t)(k0 + k) * NTOT + c * 8);
        }
        cp_commit();
    };

    issue_stage(0); issue_stage(1); issue_stage(2);

    int wm = wid & 3, wn = wid >> 2;
    int grp = lane >> 3, lrow = lane & 7;
    int rg = grp & 1, cg = grp >> 1;
    int gid = lane >> 2, tg = lane & 3;

    uint32_t a_lane0 = (uint32_t)((wm * 32 + rg * 8 + lrow) * 80 + cg * 16);
    uint32_t b_row   = (uint32_t)((rg * 8 + lrow) * 512);

    float acc[2][16][4];
#pragma unroll
    for (int mi = 0; mi < 2; mi++)
#pragma unroll
        for (int ni = 0; ni < 16; ni++)
#pragma unroll
            for (int q = 0; q < 4; q++) acc[mi][ni][q] = 0.f;

    for (int kt = 0; kt < NK; kt++) {
        asm volatile("cp.async.wait_group 2;" ::: "memory");
        __syncthreads();
        if (kt + 3 < NK) issue_stage(kt + 3);
        else cp_commit();

        uint32_t sb = smem_base + (kt & 3) * STAGE_B;
        uint32_t sbB = sb + A_STAGE_B;
#pragma unroll
        for (int kc = 0; kc < 2; kc++) {                   // two k16 steps
            uint32_t a0[4], a1[4];
            ldsm4(a0, sb + a_lane0 + kc * 32);
            ldsm4(a1, sb + a_lane0 + 1280 + kc * 32);      // +16 rows * 80B
#pragma unroll
            for (int nt = 0; nt < 8; nt++) {
                uint32_t bfr[4];
                // chunk index within 512B row: wn*16 + nt*2 + cg, swizzled
                uint32_t c = (uint32_t)(wn * 16 + nt * 2 + cg);
                uint32_t coff = (((c & 7u) ^ (uint32_t)lrow) << 4) + ((c >> 3) << 7);
                ldsm4t(bfr, sbB + b_row + kc * 8192 + coff);
                mma_f16(acc[0][nt * 2],     a0, bfr);
                mma_f16(acc[0][nt * 2 + 1], a0, bfr + 2);
                mma_f16(acc[1][nt * 2],     a1, bfr);
                mma_f16(acc[1][nt * 2 + 1], a1, bfr + 2);
            }
        }
    }

    const float* be = bias + (size_t)e * NTOT + n0;
    if (MODE == 0) {
        // store h as fp16
#pragma unroll
        for (int mi = 0; mi < 2; mi++) {
            int r0 = m0 + wm * 32 + mi * 16 + gid;
            int r1 = r0 + 8;
            __half* o0 = g_h + (size_t)r0 * NTOT + n0;
            __half* o1 = g_h + (size_t)r1 * NTOT + n0;
#pragma unroll
            for (int ni = 0; ni < 16; ni++) {
                int col = wn * 128 + (ni >> 1) * 16 + (ni & 1) * 8 + tg * 2;
                float2 bb = *(const float2*)(be + col);
                float v0 = fmaxf(acc[mi][ni][0] + bb.x, 0.f);
                float v1 = fmaxf(acc[mi][ni][1] + bb.y, 0.f);
                float v2 = fmaxf(acc[mi][ni][2] + bb.x, 0.f);
                float v3 = fmaxf(acc[mi][ni][3] + bb.y, 0.f);
                *(__half2*)(o0 + col) = __floats2half2_rn(v0, v1);
                *(__half2*)(o1 + col) = __floats2half2_rn(v2, v3);
            }
        }
    } else {
#pragma unroll
        for (int mi = 0; mi < 2; mi++) {
            int r0 = m0 + wm * 32 + mi * 16 + gid;
            int r1 = r0 + 8;
            float pw0 = g_pw[r0], pw1 = g_pw[r1];
            float* o0 = g_y + (size_t)r0 * NTOT + n0;
            float* o1 = g_y + (size_t)r1 * NTOT + n0;
#pragma unroll
            for (int ni = 0; ni < 16; ni++) {
                int col = wn * 128 + (ni >> 1) * 16 + (ni & 1) * 8 + tg * 2;
                float2 bb = *(const float2*)(be + col);
                *(float2*)(o0 + col) = make_float2(pw0 * (acc[mi][ni][0] + bb.x),
                                                   pw0 * (acc[mi][ni][1] + bb.y));
                *(float2*)(o1 + col) = make_float2(pw1 * (acc[mi][ni][2] + bb.x),
                                                   pw1 * (acc[mi][ni][3] + bb.y));
            }
        }
    }
}

// ---------------- kernel: deterministic combine ------------------------------
__global__ __launch_bounds__(256) void combine_kernel(float* __restrict__ out) {
    int t = blockIdx.x;
    int tid = threadIdx.x;
    int s0 = g_slot[2 * t];
    int s1 = g_slot[2 * t + 1];
    float4 a = ((const float4*)(g_y + (size_t)s0 * D_DIM))[tid];
    float4 b = ((const float4*)(g_y + (size_t)s1 * D_DIM))[tid];
    float4 r;
    r.x = a.x + b.x; r.y = a.y + b.y; r.z = a.z + b.z; r.w = a.w + b.w;
    ((float4*)(out + (size_t)t * D_DIM))[tid] = r;
}

// ---------------- launcher ----------------------------------------------------
extern "C" void kernel_launch(void* const* d_in, const int* in_sizes, int n_in,
                              void* d_out, int out_size) {
    const float* x      = (const float*)d_in[0];
    const float* gate_w = (const float*)d_in[1];
    const float* gate_b = (const float*)d_in[2];
    const float* w1     = (const float*)d_in[3];
    const float* b1     = (const float*)d_in[4];
    const float* w2     = (const float*)d_in[5];
    const float* b2     = (const float*)d_in[6];
    float* out = (float*)d_out;

    static bool attr_set = false;
    if (!attr_set) {
        cudaFuncSetAttribute(moe_gemm_kernel<D_DIM, H_DIM, 0>,
                             cudaFuncAttributeMaxDynamicSharedMemorySize, GEMM_SMEM);
        cudaFuncSetAttribute(moe_gemm_kernel<H_DIM, D_DIM, 1>,
                             cudaFuncAttributeMaxDynamicSharedMemorySize, GEMM_SMEM);
        attr_set = true;
    }

    init_kernel<<<(A_PAD + 255) / 256, 256>>>();
    gating_kernel<<<T_TOK / 8, 256>>>(x, gate_w, gate_b);
    offsets_kernel<<<1, 32>>>();
    scatter_kernel<<<A_TOT / 256, 256>>>();

    __half* xh_p;  cudaGetSymbolAddress((void**)&xh_p,  g_xh);
    __half* w1h_p; cudaGetSymbolAddress((void**)&w1h_p, g_w1h);
    __half* w2h_p; cudaGetSymbolAddress((void**)&w2h_p, g_w2h);
    cvt_kernel<<<(T_TOK * D_DIM / 4) / 256, 256>>>(x, (__half2*)xh_p);
    cvt_kernel<<<(E_NUM * (size_t)D_DIM * H_DIM / 4) / 256, 256>>>(w1, (__half2*)w1h_p);
    cvt_kernel<<<(E_NUM * (size_t)D_DIM * H_DIM / 4) / 256, 256>>>(w2, (__half2*)w2h_p);

    moe_gemm_kernel<D_DIM, H_DIM, 0><<<dim3(MT_TILES, H_DIM / 256), 256, GEMM_SMEM>>>(w1h_p, b1);
    moe_gemm_kernel<H_DIM, D_DIM, 1><<<dim3(MT_TILES, D_DIM / 256), 256, GEMM_SMEM>>>(w2h_p, b2);

    combine_kernel<<<T_TOK, 256>>>(out);
}

// round 16
// speedup vs baseline: 1.2625x; 1.2625x over previous
#include <cuda_runtime.h>
#include <cuda_fp16.h>
#include <math.h>
#include <stdint.h>

// Problem constants: B=4, S=2048, D=1024, E=8, K=2, H=2048
#define T_TOK 8192
#define D_DIM 1024
#define H_DIM 2048
#define E_NUM 8
#define A_TOT (2 * T_TOK)             // 16384 assignments
#define A_PAD (A_TOT + E_NUM * 128)   // 17408 padded rows
#define MT_TILES (A_PAD / 128)        // 136 m-tiles

// ---------------- scratch (device globals; no allocations) ------------------
__device__ int   g_topi[A_TOT];
__device__ float g_topw[A_TOT];
__device__ int   g_cnt[E_NUM];
__device__ int   g_poff[E_NUM + 1];
__device__ int   g_cursor[E_NUM];
__device__ int   g_perm[A_PAD];
__device__ float g_pw[A_PAD];
__device__ __half g_xh [(size_t)T_TOK * D_DIM];            // x fp16, 17 MB
__device__ __half g_w1h[(size_t)E_NUM * D_DIM * H_DIM];    // w1 fp16, 34 MB
__device__ __half g_w2h[(size_t)E_NUM * D_DIM * H_DIM];    // w2 fp16, 34 MB
__device__ __half g_h  [(size_t)A_PAD * H_DIM];            // hidden fp16, 71 MB

// ---------------- PTX helpers (generic sm_80+/sm_90+ only) ------------------
__device__ __forceinline__ uint32_t smem_u32(const void* p) {
    uint32_t a;
    asm("{ .reg .u64 t; cvta.to.shared.u64 t, %1; cvt.u32.u64 %0, t; }" : "=r"(a) : "l"(p));
    return a;
}
__device__ __forceinline__ void cp_async16(uint32_t dst, const void* src) {
    asm volatile("cp.async.cg.shared.global [%0], [%1], 16;" :: "r"(dst), "l"(src) : "memory");
}
__device__ __forceinline__ void cp_commit() {
    asm volatile("cp.async.commit_group;" ::: "memory");
}
__device__ __forceinline__ void ldsm4(uint32_t* r, uint32_t a) {
    asm volatile("ldmatrix.sync.aligned.m8n8.x4.shared.b16 {%0,%1,%2,%3}, [%4];"
                 : "=r"(r[0]), "=r"(r[1]), "=r"(r[2]), "=r"(r[3]) : "r"(a));
}
__device__ __forceinline__ void ldsm4t(uint32_t* r, uint32_t a) {
    asm volatile("ldmatrix.sync.aligned.m8n8.x4.trans.shared.b16 {%0,%1,%2,%3}, [%4];"
                 : "=r"(r[0]), "=r"(r[1]), "=r"(r[2]), "=r"(r[3]) : "r"(a));
}
__device__ __forceinline__ void mma_f16(float* c, const uint32_t* a, const uint32_t* b) {
    asm volatile(
        "mma.sync.aligned.m16n8k16.row.col.f32.f16.f16.f32 "
        "{%0,%1,%2,%3}, {%4,%5,%6,%7}, {%8,%9}, {%0,%1,%2,%3};"
        : "+f"(c[0]), "+f"(c[1]), "+f"(c[2]), "+f"(c[3])
        : "r"(a[0]), "r"(a[1]), "r"(a[2]), "r"(a[3]), "r"(b[0]), "r"(b[1]));
}
__device__ __forceinline__ void red_add_v2(float* addr, float x, float y) {
    asm volatile("red.global.add.v2.f32 [%0], {%1, %2};"
                 :: "l"(addr), "f"(x), "f"(y) : "memory");
}

// ---------------- kernel: init (zero out + counters + padded perm/pw) -------
__global__ __launch_bounds__(256) void init_kernel(float4* __restrict__ outz) {
    int i = blockIdx.x * 256 + threadIdx.x;
    if (i < T_TOK * D_DIM / 4) outz[i] = make_float4(0.f, 0.f, 0.f, 0.f);
    if (i < A_PAD) { g_perm[i] = 0; g_pw[i] = 0.f; }
    if (i < E_NUM) g_cnt[i] = 0;
}

// ---------------- kernel: fp32 -> fp16 convert ------------------------------
__global__ __launch_bounds__(256) void cvt_kernel(const float* __restrict__ src,
                                                  __half2* __restrict__ dst) {
    int i = blockIdx.x * 256 + threadIdx.x;      // one float4 per thread
    float4 v = ((const float4*)src)[i];
    dst[2 * i]     = __floats2half2_rn(v.x, v.y);
    dst[2 * i + 1] = __floats2half2_rn(v.z, v.w);
}

// ---------------- kernel: gating (softmax + top-2 + counts) -----------------
__global__ __launch_bounds__(256) void gating_kernel(
    const float* __restrict__ x, const float* __restrict__ gw, const float* __restrict__ gb)
{
    __shared__ float s_gw[D_DIM * E_NUM];
    int tid = threadIdx.x;
    for (int i = tid; i < D_DIM * E_NUM; i += blockDim.x) s_gw[i] = gw[i];
    __syncthreads();

    int warp = tid >> 5, lane = tid & 31;
    int t = blockIdx.x * 8 + warp;
    if (t >= T_TOK) return;

    float acc[E_NUM];
#pragma unroll
    for (int e = 0; e < E_NUM; e++) acc[e] = 0.f;
    const float* xr = x + (size_t)t * D_DIM;
    for (int d = lane; d < D_DIM; d += 32) {
        float xv = xr[d];
        const float* g = s_gw + d * E_NUM;
#pragma unroll
        for (int e = 0; e < E_NUM; e++) acc[e] += xv * g[e];
    }
#pragma unroll
    for (int e = 0; e < E_NUM; e++)
#pragma unroll
        for (int o = 16; o > 0; o >>= 1)
            acc[e] += __shfl_xor_sync(0xffffffffu, acc[e], o);

    if (lane == 0) {
        float logits[E_NUM];
#pragma unroll
        for (int e = 0; e < E_NUM; e++) logits[e] = acc[e] + gb[e];
        float mx = logits[0];
#pragma unroll
        for (int e = 1; e < E_NUM; e++) mx = fmaxf(mx, logits[e]);
        float p[E_NUM], s = 0.f;
#pragma unroll
        for (int e = 0; e < E_NUM; e++) { p[e] = expf(logits[e] - mx); s += p[e]; }
        float inv_s = 1.f / s;
#pragma unroll
        for (int e = 0; e < E_NUM; e++) p[e] *= inv_s;

        int i0 = 0;
#pragma unroll
        for (int e = 1; e < E_NUM; e++) if (p[e] > p[i0]) i0 = e;
        int i1 = (i0 == 0) ? 1 : 0;
#pragma unroll
        for (int e = 0; e < E_NUM; e++)
            if (e != i0 && p[e] > p[i1]) i1 = e;

        float w0 = p[i0], w1 = p[i1];
        float inv = 1.f / (w0 + w1 + 1e-9f);
        g_topi[2 * t] = i0;     g_topw[2 * t] = w0 * inv;
        g_topi[2 * t + 1] = i1; g_topw[2 * t + 1] = w1 * inv;
        atomicAdd(&g_cnt[i0], 1);
        atomicAdd(&g_cnt[i1], 1);
    }
}

// ---------------- kernel: padded offsets -------------------------------------
__global__ void offsets_kernel() {
    if (threadIdx.x == 0) {
        int o = 0;
        for (int e = 0; e < E_NUM; e++) {
            g_poff[e] = o;
            g_cursor[e] = o;
            o += ((g_cnt[e] + 127) & ~127);
        }
        g_poff[E_NUM] = o;
    }
}

// ---------------- kernel: scatter --------------------------------------------
__global__ void scatter_kernel() {
    int a = blockIdx.x * blockDim.x + threadIdx.x;
    if (a >= A_TOT) return;
    int e = g_topi[a];
    int pos = atomicAdd(&g_cursor[e], 1);
    g_perm[pos] = a >> 1;
    g_pw[pos] = g_topw[a];
}

// ---------------- fp16 mma grouped GEMM (R9 config: 128x128x32, 2 CTA/SM) ---
// MODE 0: h = relu(xh[perm] @ w1h + b1)  (A gathered via g_perm)
// MODE 1: out[perm[slot]] += pw * (h @ w2h + b2)   (red.global.add.v2.f32)
#define A_STAGE_B (128 * 80)                  // 10240
#define B_STAGE_B (32 * 256)                  // 8192
#define STAGE_B (A_STAGE_B + B_STAGE_B)       // 18432
#define GEMM_SMEM (4 * STAGE_B)               // 73728

template<int KDIM, int NTOT, int MODE>
__global__ __launch_bounds__(256, 2) void moe_gemm_kernel(
    const __half* __restrict__ W, const float* __restrict__ bias,
    float* __restrict__ yout)
{
    constexpr int NK = KDIM / 32;
    extern __shared__ char smraw[];
    __shared__ int s_perm[128];
    uint32_t smem_base = smem_u32(smraw);

    int tid = threadIdx.x, wid = tid >> 5, lane = tid & 31;
    int m0 = blockIdx.x * 128;

    int e = -1;
#pragma unroll
    for (int i = 0; i < E_NUM; i++)
        if (m0 >= g_poff[i] && m0 < g_poff[i + 1]) e = i;
    if (e < 0) return;
    int n0 = blockIdx.y * 128;

    if (MODE == 0) {
        if (tid < 128) s_perm[tid] = g_perm[m0 + tid];
        __syncthreads();
    }

    const __half* Ag = g_h + (size_t)m0 * KDIM;            // MODE 1 A base
    const __half* Bw = W + (size_t)e * KDIM * NTOT + n0;   // [k][n] row-major

    auto issue_stage = [&](int kt) {
        uint32_t sb = smem_base + (kt & 3) * STAGE_B;
        int k0 = kt * 32;
#pragma unroll
        for (int ii = 0; ii < 2; ii++) {                   // A: 512 chunks
            int i = tid + ii * 256;
            int m = i >> 2, c = i & 3;
            const __half* src = (MODE == 0)
                ? g_xh + (size_t)s_perm[m] * KDIM + k0 + c * 8
                : Ag + (size_t)m * KDIM + k0 + c * 8;
            cp_async16(sb + m * 80 + c * 16, src);
        }
        uint32_t sbB = sb + A_STAGE_B;
#pragma unroll
        for (int ii = 0; ii < 2; ii++) {                   // B: 512 chunks
            int i = tid + ii * 256;
            int k = i >> 4, c = i & 15;
            cp_async16(sbB + k * 256 + ((c ^ (k & 7)) << 4),
                       Bw + (size_t)(k0 + k) * NTOT + c * 8);
        }
        cp_commit();
    };

    issue_stage(0); issue_stage(1); issue_stage(2);

    int wm = wid & 3, wn = wid >> 2;
    int grp = lane >> 3, lrow = lane & 7;
    int rg = grp & 1, cg = grp >> 1;
    int gid = lane >> 2, tg = lane & 3;

    uint32_t a_lane0 = (uint32_t)((wm * 32 + rg * 8 + lrow) * 80 + cg * 16);
    uint32_t b_row   = (uint32_t)((rg * 8 + lrow) * 256);

    float acc[2][8][4];
#pragma unroll
    for (int mi = 0; mi < 2; mi++)
#pragma unroll
        for (int ni = 0; ni < 8; ni++)
#pragma unroll
            for (int q = 0; q < 4; q++) acc[mi][ni][q] = 0.f;

    for (int kt = 0; kt < NK; kt++) {
        asm volatile("cp.async.wait_group 2;" ::: "memory");
        __syncthreads();
        if (kt + 3 < NK) issue_stage(kt + 3);
        else cp_commit();

        uint32_t sb = smem_base + (kt & 3) * STAGE_B;
        uint32_t sbB = sb + A_STAGE_B;
#pragma unroll
        for (int kc = 0; kc < 2; kc++) {                   // two k16 steps
            uint32_t a0[4], a1[4];
            ldsm4(a0, sb + a_lane0 + kc * 32);
            ldsm4(a1, sb + a_lane0 + 1280 + kc * 32);      // +16 rows * 80B
#pragma unroll
            for (int nt = 0; nt < 4; nt++) {
                uint32_t bfr[4];
                uint32_t c = (uint32_t)(wn * 8 + nt * 2 + cg);
                ldsm4t(bfr, sbB + b_row + kc * 4096 + ((c ^ (uint32_t)lrow) << 4));
                mma_f16(acc[0][nt * 2],     a0, bfr);
                mma_f16(acc[0][nt * 2 + 1], a0, bfr + 2);
                mma_f16(acc[1][nt * 2],     a1, bfr);
                mma_f16(acc[1][nt * 2 + 1], a1, bfr + 2);
            }
        }
    }

    const float* be = bias + (size_t)e * NTOT + n0;
    if (MODE == 0) {
        // store h as fp16
#pragma unroll
        for (int mi = 0; mi < 2; mi++) {
            int r0 = m0 + wm * 32 + mi * 16 + gid;
            int r1 = r0 + 8;
            __half* o0 = g_h + (size_t)r0 * NTOT + n0;
            __half* o1 = g_h + (size_t)r1 * NTOT + n0;
#pragma unroll
            for (int ni = 0; ni < 8; ni++) {
                int col = wn * 64 + (ni >> 1) * 16 + (ni & 1) * 8 + tg * 2;
                float2 bb = *(const float2*)(be + col);
                float v0 = fmaxf(acc[mi][ni][0] + bb.x, 0.f);
                float v1 = fmaxf(acc[mi][ni][1] + bb.y, 0.f);
                float v2 = fmaxf(acc[mi][ni][2] + bb.x, 0.f);
                float v3 = fmaxf(acc[mi][ni][3] + bb.y, 0.f);
                *(__half2*)(o0 + col) = __floats2half2_rn(v0, v1);
                *(__half2*)(o1 + col) = __floats2half2_rn(v2, v3);
            }
        }
    } else {
        // reduce directly into the output at the token row (2 adds/elem, exact)
#pragma unroll
        for (int mi = 0; mi < 2; mi++) {
            int r0 = m0 + wm * 32 + mi * 16 + gid;
            int r1 = r0 + 8;
            float pw0 = g_pw[r0], pw1 = g_pw[r1];
            int t0 = g_perm[r0], t1 = g_perm[r1];
            float* o0 = yout + (size_t)t0 * NTOT + n0;
            float* o1 = yout + (size_t)t1 * NTOT + n0;
#pragma unroll
            for (int ni = 0; ni < 8; ni++) {
                int col = wn * 64 + (ni >> 1) * 16 + (ni & 1) * 8 + tg * 2;
                float2 bb = *(const float2*)(be + col);
                if (pw0 != 0.f)
                    red_add_v2(o0 + col, pw0 * (acc[mi][ni][0] + bb.x),
                                         pw0 * (acc[mi][ni][1] + bb.y));
                if (pw1 != 0.f)
                    red_add_v2(o1 + col, pw1 * (acc[mi][ni][2] + bb.x),
                                         pw1 * (acc[mi][ni][3] + bb.y));
            }
        }
    }
}

// ---------------- launcher ----------------------------------------------------
extern "C" void kernel_launch(void* const* d_in, const int* in_sizes, int n_in,
                              void* d_out, int out_size) {
    const float* x      = (const float*)d_in[0];
    const float* gate_w = (const float*)d_in[1];
    const float* gate_b = (const float*)d_in[2];
    const float* w1     = (const float*)d_in[3];
    const float* b1     = (const float*)d_in[4];
    const float* w2     = (const float*)d_in[5];
    const float* b2     = (const float*)d_in[6];
    float* out = (float*)d_out;

    static cudaStream_t s1 = nullptr;
    static cudaEvent_t evA = nullptr, evB = nullptr, evC = nullptr;
    if (!s1) {
        cudaStreamCreateWithFlags(&s1, cudaStreamNonBlocking);
        cudaEventCreateWithFlags(&evA, cudaEventDisableTiming);
        cudaEventCreateWithFlags(&evB, cudaEventDisableTiming);
        cudaEventCreateWithFlags(&evC, cudaEventDisableTiming);
        cudaFuncSetAttribute(moe_gemm_kernel<D_DIM, H_DIM, 0>,
                             cudaFuncAttributeMaxDynamicSharedMemorySize, GEMM_SMEM);
        cudaFuncSetAttribute(moe_gemm_kernel<H_DIM, D_DIM, 1>,
                             cudaFuncAttributeMaxDynamicSharedMemorySize, GEMM_SMEM);
    }

    __half* xh_p;  cudaGetSymbolAddress((void**)&xh_p,  g_xh);
    __half* w1h_p; cudaGetSymbolAddress((void**)&w1h_p, g_w1h);
    __half* w2h_p; cudaGetSymbolAddress((void**)&w2h_p, g_w2h);

    // fork: conversions on s1, routing chain on the main stream
    cudaEventRecord(evA, 0);
    cudaStreamWaitEvent(s1, evA, 0);
    cvt_kernel<<<(T_TOK * D_DIM / 4) / 256, 256, 0, s1>>>(x, (__half2*)xh_p);
    cvt_kernel<<<(E_NUM * (size_t)D_DIM * H_DIM / 4) / 256, 256, 0, s1>>>(w1, (__half2*)w1h_p);
    cudaEventRecord(evB, s1);
    cvt_kernel<<<(E_NUM * (size_t)D_DIM * H_DIM / 4) / 256, 256, 0, s1>>>(w2, (__half2*)w2h_p);
    cudaEventRecord(evC, s1);

    // routing chain (main stream), also zeros d_out for the reduction epilogue
    init_kernel<<<(T_TOK * D_DIM / 4 + 255) / 256, 256>>>((float4*)out);
    gating_kernel<<<T_TOK / 8, 256>>>(x, gate_w, gate_b);
    offsets_kernel<<<1, 32>>>();
    scatter_kernel<<<A_TOT / 256, 256>>>();

    // GEMM1 needs xh + w1h
    cudaStreamWaitEvent(0, evB, 0);
    moe_gemm_kernel<D_DIM, H_DIM, 0>
        <<<dim3(MT_TILES, H_DIM / 128), 256, GEMM_SMEM>>>(w1h_p, b1, nullptr);

    // GEMM2 needs w2h (cvt_w2 overlapped with GEMM1)
    cudaStreamWaitEvent(0, evC, 0);
    moe_gemm_kernel<H_DIM, D_DIM, 1>
        <<<dim3(MT_TILES, D_DIM / 128), 256, GEMM_SMEM>>>(w2h_p, b2, out);
}